// round 2
// baseline (speedup 1.0000x reference)
#include <cuda_runtime.h>
#include <cuda_bf16.h>
#include <cstdint>
#include <cstddef>

// ----------------------------------------------------------------------------
// DiT block: B=1024, S=64, D=768, HID=3072, 12 heads x 64 head_dim
// Round 1: fp32 SIMT pipeline, fused epilogues, correctness-first baseline.
// ----------------------------------------------------------------------------

#define Bq    1024
#define Sq    64
#define Dq    768
#define HIDq  3072
#define NHq   12
#define HDq   64
#define BSq   (Bq * Sq)            // 65536 tokens
#define MODW  (6 * Dq)             // 4608

// ---------------- scratch (device globals; no runtime allocation) -----------
__device__ float g_mishc[(size_t)Bq * Dq];            //   3 MB
__device__ float g_mod  [(size_t)Bq * MODW];          //  19 MB
__device__ float g_h    [(size_t)BSq * Dq];           // 201 MB (h1 / h2)
__device__ float g_qkv  [(size_t)BSq * 3 * Dq];       // 604 MB
__device__ float g_attn [(size_t)BSq * Dq];           // 201 MB
__device__ float g_x2   [(size_t)BSq * Dq];           // 201 MB
__device__ float g_ffn  [(size_t)BSq * HIDq];         // 805 MB

// ---------------- helpers ----------------------------------------------------
__device__ __forceinline__ float mishf(float v) {
    float sp = (v > 20.0f) ? v : log1pf(__expf(v));
    return v * tanhf(sp);
}

// ---------------- elementwise mish(c) ----------------------------------------
__global__ void mish_kernel(const float* __restrict__ in, float* __restrict__ outp, int n) {
    int i = blockIdx.x * blockDim.x + threadIdx.x;
    if (i < n) outp[i] = mishf(in[i]);
}

// ---------------- LayerNorm + modulation -------------------------------------
// Y[t, :] = LN(X[t, :]) * (1 + mod[b, scaleOff + :]) + mod[b, shiftOff + :]
__global__ __launch_bounds__(256)
void ln_mod_kernel(const float* __restrict__ X, const float* __restrict__ mod,
                   float* __restrict__ Y, int shiftOff, int scaleOff) {
    __shared__ float red [8];
    __shared__ float red2[8];
    __shared__ float stats[2];
    int t   = blockIdx.x;
    int tid = threadIdx.x;
    const float* xr = X + (size_t)t * Dq;
    float v0 = xr[tid], v1 = xr[tid + 256], v2 = xr[tid + 512];
    float s  = v0 + v1 + v2;
    float sq = v0 * v0 + v1 * v1 + v2 * v2;
    #pragma unroll
    for (int o = 16; o > 0; o >>= 1) {
        s  += __shfl_xor_sync(0xffffffffu, s,  o);
        sq += __shfl_xor_sync(0xffffffffu, sq, o);
    }
    int w = tid >> 5, lane = tid & 31;
    if (lane == 0) { red[w] = s; red2[w] = sq; }
    __syncthreads();
    if (tid == 0) {
        float S = 0.f, SQ = 0.f;
        #pragma unroll
        for (int i = 0; i < 8; i++) { S += red[i]; SQ += red2[i]; }
        float mean = S * (1.0f / Dq);
        float var  = SQ * (1.0f / Dq) - mean * mean;
        stats[0] = mean;
        stats[1] = rsqrtf(var + 1e-5f);
    }
    __syncthreads();
    float mean = stats[0], r = stats[1];
    const float* mrow = mod + (size_t)(t >> 6) * MODW;
    float* yr = Y + (size_t)t * Dq;
    yr[tid]       = (v0 - mean) * r * (1.0f + mrow[scaleOff + tid])       + mrow[shiftOff + tid];
    yr[tid + 256] = (v1 - mean) * r * (1.0f + mrow[scaleOff + tid + 256]) + mrow[shiftOff + tid + 256];
    yr[tid + 512] = (v2 - mean) * r * (1.0f + mrow[scaleOff + tid + 512]) + mrow[shiftOff + tid + 512];
}

// ---------------- tiled fp32 GEMM with fused epilogues ------------------------
// C[M,N] = epi(A[M,K] @ B[K,N] + bias[N])
// EPI 0: bias only
// EPI 1: mish(acc + bias)
// EPI 2: resid[m,n] + mod[m>>6, modOff + n] * (acc + bias)
#define BM 128
#define BN 128
#define BK 16
#define TM 8
#define TN 8

template <int EPI>
__global__ __launch_bounds__(256, 2)
void gemm_k(const float* __restrict__ A, const float* __restrict__ B,
            const float* __restrict__ bias, float* __restrict__ C,
            int M, int N, int K,
            const float* __restrict__ mod, int modOff,
            const float* __restrict__ resid) {
    __shared__ float As[BK][BM];
    __shared__ float Bs[BK][BN];

    const int tid   = threadIdx.x;
    const int tx    = tid & 15;   // 0..15 -> col groups of 8
    const int ty    = tid >> 4;   // 0..15 -> row groups of 8
    const int mBase = blockIdx.y * BM;
    const int nBase = blockIdx.x * BN;

    float acc[TM][TN];
    #pragma unroll
    for (int i = 0; i < TM; i++)
        #pragma unroll
        for (int j = 0; j < TN; j++) acc[i][j] = 0.f;

    const float* Aptr = A + (size_t)mBase * K;
    const float* Bptr = B + nBase;

    for (int k0 = 0; k0 < K; k0 += BK) {
        // A tile: 128x16 = 512 float4, 2 per thread, store transposed
        #pragma unroll
        for (int it = 0; it < 2; it++) {
            int ia  = tid + it * 256;
            int row = ia >> 2;
            int kg  = ia & 3;
            float4 v = *reinterpret_cast<const float4*>(Aptr + (size_t)row * K + k0 + kg * 4);
            As[kg * 4 + 0][row] = v.x;
            As[kg * 4 + 1][row] = v.y;
            As[kg * 4 + 2][row] = v.z;
            As[kg * 4 + 3][row] = v.w;
        }
        // B tile: 16x128 = 512 float4, 2 per thread
        #pragma unroll
        for (int it = 0; it < 2; it++) {
            int ib   = tid + it * 256;
            int krow = ib >> 5;
            int ng   = ib & 31;
            *reinterpret_cast<float4*>(&Bs[krow][ng * 4]) =
                *reinterpret_cast<const float4*>(Bptr + (size_t)(k0 + krow) * N + ng * 4);
        }
        __syncthreads();
        #pragma unroll
        for (int kk = 0; kk < BK; kk++) {
            float a[TM], b[TN];
            #pragma unroll
            for (int i = 0; i < TM; i++) a[i] = As[kk][ty * TM + i];
            #pragma unroll
            for (int j = 0; j < TN; j++) b[j] = Bs[kk][tx * TN + j];
            #pragma unroll
            for (int i = 0; i < TM; i++)
                #pragma unroll
                for (int j = 0; j < TN; j++)
                    acc[i][j] += a[i] * b[j];
        }
        __syncthreads();
    }

    // epilogue
    #pragma unroll
    for (int i = 0; i < TM; i++) {
        int m = mBase + ty * TM + i;
        const float* mrow = (EPI == 2) ? (mod + (size_t)(m >> 6) * MODW + modOff) : nullptr;
        #pragma unroll
        for (int j = 0; j < TN; j++) {
            int n = nBase + tx * TN + j;
            float v = acc[i][j] + bias[n];
            if (EPI == 1) {
                v = mishf(v);
            } else if (EPI == 2) {
                v = resid[(size_t)m * N + n] + mrow[n] * v;
            }
            C[(size_t)m * N + n] = v;
        }
    }
}

// ---------------- attention: one block per (head, batch) ----------------------
// qkv layout per token: [3, 12 heads, 64] columns. S=64, head_dim=64.
__global__ __launch_bounds__(256)
void attn_kernel(const float* __restrict__ QKV, float* __restrict__ O) {
    __shared__ float qs [64][64];   // q rows; reused for v rows
    __shared__ float ksT[64][64];   // transposed k: [d][j]
    __shared__ float psT[64][64];   // transposed probs: [j][i]
    int h   = blockIdx.x;
    int b   = blockIdx.y;
    int tid = threadIdx.x;
    size_t base = (size_t)b * 64 * (3 * Dq) + (size_t)h * HDq;

    #pragma unroll
    for (int it = 0; it < 4; it++) {
        int idx = tid + it * 256;
        int row = idx >> 4;       // token
        int cg  = idx & 15;       // d group (float4)
        float4 q4 = *reinterpret_cast<const float4*>(QKV + base + (size_t)row * (3 * Dq) + cg * 4);
        *reinterpret_cast<float4*>(&qs[row][cg * 4]) = q4;
        float4 k4 = *reinterpret_cast<const float4*>(QKV + base + (size_t)row * (3 * Dq) + Dq + cg * 4);
        ksT[cg * 4 + 0][row] = k4.x;
        ksT[cg * 4 + 1][row] = k4.y;
        ksT[cg * 4 + 2][row] = k4.z;
        ksT[cg * 4 + 3][row] = k4.w;
    }
    __syncthreads();

    int i  = tid >> 2;    // query row 0..63
    int jg = tid & 3;     // key-column group
    float sc[16];
    #pragma unroll
    for (int jj = 0; jj < 16; jj++) {
        int j = jg * 16 + jj;
        float acc = 0.f;
        #pragma unroll
        for (int d = 0; d < 64; d++) acc += qs[i][d] * ksT[d][j];
        sc[jj] = acc * 0.125f;   // head_dim^-0.5 = 1/8
    }
    float mx = sc[0];
    #pragma unroll
    for (int jj = 1; jj < 16; jj++) mx = fmaxf(mx, sc[jj]);
    mx = fmaxf(mx, __shfl_xor_sync(0xffffffffu, mx, 1));
    mx = fmaxf(mx, __shfl_xor_sync(0xffffffffu, mx, 2));
    float sum = 0.f;
    #pragma unroll
    for (int jj = 0; jj < 16; jj++) { sc[jj] = __expf(sc[jj] - mx); sum += sc[jj]; }
    sum += __shfl_xor_sync(0xffffffffu, sum, 1);
    sum += __shfl_xor_sync(0xffffffffu, sum, 2);
    float rinv = 1.0f / sum;
    #pragma unroll
    for (int jj = 0; jj < 16; jj++) psT[jg * 16 + jj][i] = sc[jj] * rinv;
    __syncthreads();

    // overwrite qs with v (all phase-1 reads completed at the barrier)
    #pragma unroll
    for (int it = 0; it < 4; it++) {
        int idx = tid + it * 256;
        int row = idx >> 4;
        int cg  = idx & 15;
        *reinterpret_cast<float4*>(&qs[row][cg * 4]) =
            *reinterpret_cast<const float4*>(QKV + base + (size_t)row * (3 * Dq) + 2 * Dq + cg * 4);
    }
    __syncthreads();

    int d0 = (tid & 3) * 16;
    float o[16];
    #pragma unroll
    for (int dd = 0; dd < 16; dd++) o[dd] = 0.f;
    #pragma unroll
    for (int j = 0; j < 64; j++) {
        float p = psT[j][i];
        #pragma unroll
        for (int dd = 0; dd < 16; dd++) o[dd] += p * qs[j][d0 + dd];
    }
    float* orow = O + (size_t)(b * 64 + i) * Dq + h * HDq + d0;
    #pragma unroll
    for (int dd = 0; dd < 16; dd += 4)
        *reinterpret_cast<float4*>(orow + dd) = make_float4(o[dd], o[dd + 1], o[dd + 2], o[dd + 3]);
}

// ---------------- launch ------------------------------------------------------
extern "C" void kernel_launch(void* const* d_in, const int* in_sizes, int n_in,
                              void* d_out, int out_size) {
    const float* x     = (const float*)d_in[0];
    const float* c     = (const float*)d_in[1];
    const float* W_mod = (const float*)d_in[2];
    const float* b_mod = (const float*)d_in[3];
    const float* W_qkv = (const float*)d_in[4];
    const float* b_qkv = (const float*)d_in[5];
    const float* W_out = (const float*)d_in[6];
    const float* b_out = (const float*)d_in[7];
    const float* W_f1  = (const float*)d_in[8];
    const float* b_f1  = (const float*)d_in[9];
    const float* W_f2  = (const float*)d_in[10];
    const float* b_f2  = (const float*)d_in[11];
    float* out = (float*)d_out;

    float *mishc, *modp, *hbuf, *qkv, *attn, *x2, *ffn;
    cudaGetSymbolAddress((void**)&mishc, g_mishc);
    cudaGetSymbolAddress((void**)&modp,  g_mod);
    cudaGetSymbolAddress((void**)&hbuf,  g_h);
    cudaGetSymbolAddress((void**)&qkv,   g_qkv);
    cudaGetSymbolAddress((void**)&attn,  g_attn);
    cudaGetSymbolAddress((void**)&x2,    g_x2);
    cudaGetSymbolAddress((void**)&ffn,   g_ffn);

    // 1) mish(c)
    {
        int n = Bq * Dq;
        mish_kernel<<<(n + 255) / 256, 256>>>(c, mishc, n);
    }
    // 2) mod = mish(c) @ W_mod + b_mod      [1024 x 4608]
    gemm_k<0><<<dim3(MODW / BN, Bq / BM), 256>>>(mishc, W_mod, b_mod, modp,
                                                 Bq, MODW, Dq, nullptr, 0, nullptr);
    // 3) h1 = LN(x)*(1+scale1)+shift1       (shift1 @0, scale1 @D)
    ln_mod_kernel<<<BSq, 256>>>(x, modp, hbuf, 0, Dq);
    // 4) qkv = h1 @ W_qkv + b_qkv           [65536 x 2304]
    gemm_k<0><<<dim3(3 * Dq / BN, BSq / BM), 256>>>(hbuf, W_qkv, b_qkv, qkv,
                                                    BSq, 3 * Dq, Dq, nullptr, 0, nullptr);
    // 5) attention per (head, batch)
    attn_kernel<<<dim3(NHq, Bq), 256>>>(qkv, attn);
    // 6) x2 = x + gate1 * (attn @ W_out + b_out)   (gate1 @2D)
    gemm_k<2><<<dim3(Dq / BN, BSq / BM), 256>>>(attn, W_out, b_out, x2,
                                                BSq, Dq, Dq, modp, 2 * Dq, x);
    // 7) h2 = LN(x2)*(1+scale2)+shift2      (shift2 @3D, scale2 @4D)
    ln_mod_kernel<<<BSq, 256>>>(x2, modp, hbuf, 3 * Dq, 4 * Dq);
    // 8) ffn = mish(h2 @ W_f1 + b_f1)       [65536 x 3072]
    gemm_k<1><<<dim3(HIDq / BN, BSq / BM), 256>>>(hbuf, W_f1, b_f1, ffn,
                                                  BSq, HIDq, Dq, nullptr, 0, nullptr);
    // 9) out = x2 + gate2 * (ffn @ W_f2 + b_f2)    (gate2 @5D)
    gemm_k<2><<<dim3(Dq / BN, BSq / BM), 256>>>(ffn, W_f2, b_f2, out,
                                                BSq, Dq, HIDq, modp, 5 * Dq, x2);
}

// round 5
// speedup vs baseline: 3.2580x; 3.2580x over previous
#include <cuda_runtime.h>
#include <cuda_bf16.h>
#include <cstdint>
#include <cstddef>

// ----------------------------------------------------------------------------
// DiT block: B=1024, S=64, D=768, HID=3072, 12 heads x 64 hd
// Round 5: GEMMs via mma.sync tf32 (baseline PTX; tcgen05 unavailable on this
// toolchain target), cp.async double-buffered, swizzled conflict-free smem.
// ----------------------------------------------------------------------------

#define Bq    1024
#define Sq    64
#define Dq    768
#define HIDq  3072
#define NHq   12
#define HDq   64
#define BSq   (Bq * Sq)
#define MODW  (6 * Dq)

// ---------------- scratch -----------------------------------------------------
__device__ float g_mishc[(size_t)Bq * Dq];
__device__ float g_mod  [(size_t)Bq * MODW];
__device__ float g_h    [(size_t)BSq * Dq];
__device__ float g_qkv  [(size_t)BSq * 3 * Dq];
__device__ float g_attn [(size_t)BSq * Dq];
__device__ float g_x2   [(size_t)BSq * Dq];
__device__ float g_ffn  [(size_t)BSq * HIDq];
// transposed weights [N, K] fp32
#define WT_QKV_OFF 0
#define WT_OUT_OFF (WT_QKV_OFF + 2304 * 768)
#define WT_F1_OFF  (WT_OUT_OFF + 768 * 768)
#define WT_F2_OFF  (WT_F1_OFF  + 3072 * 768)
#define WT_MOD_OFF (WT_F2_OFF  + 768 * 3072)
#define WT_TOTAL   (WT_MOD_OFF + 4608 * 768)
__device__ float g_wt[(size_t)WT_TOTAL];

// ---------------- helpers -----------------------------------------------------
__device__ __forceinline__ uint32_t smem_u32(const void* p) {
    uint32_t a;
    asm("{ .reg .u64 t; cvta.to.shared.u64 t, %1; cvt.u32.u64 %0, t; }" : "=r"(a) : "l"(p));
    return a;
}
__device__ __forceinline__ float mishf(float v) {
    float sp = (v > 20.0f) ? v : log1pf(__expf(v));
    return v * tanhf(sp);
}

__global__ void mish_kernel(const float* __restrict__ in, float* __restrict__ outp, int n) {
    int i = blockIdx.x * blockDim.x + threadIdx.x;
    if (i < n) outp[i] = mishf(in[i]);
}

// W[K,N] -> Wt[N,K]
__global__ __launch_bounds__(256)
void transpose_k(const float* __restrict__ W, float* __restrict__ Wt, int K, int N) {
    __shared__ float t[32][33];
    int n0 = blockIdx.x * 32, k0 = blockIdx.y * 32;
    int x = threadIdx.x, y = threadIdx.y;
    #pragma unroll
    for (int i = 0; i < 32; i += 8) t[y + i][x] = W[(size_t)(k0 + y + i) * N + n0 + x];
    __syncthreads();
    #pragma unroll
    for (int i = 0; i < 32; i += 8) Wt[(size_t)(n0 + y + i) * K + k0 + x] = t[x][y + i];
}

// ---------------- LayerNorm + modulation --------------------------------------
__global__ __launch_bounds__(256)
void ln_mod_kernel(const float* __restrict__ X, const float* __restrict__ mod,
                   float* __restrict__ Y, int shiftOff, int scaleOff) {
    __shared__ float red [8];
    __shared__ float red2[8];
    __shared__ float stats[2];
    int t   = blockIdx.x;
    int tid = threadIdx.x;
    const float* xr = X + (size_t)t * Dq;
    float v0 = xr[tid], v1 = xr[tid + 256], v2 = xr[tid + 512];
    float s  = v0 + v1 + v2;
    float sq = v0 * v0 + v1 * v1 + v2 * v2;
    #pragma unroll
    for (int o = 16; o > 0; o >>= 1) {
        s  += __shfl_xor_sync(0xffffffffu, s,  o);
        sq += __shfl_xor_sync(0xffffffffu, sq, o);
    }
    int w = tid >> 5, lane = tid & 31;
    if (lane == 0) { red[w] = s; red2[w] = sq; }
    __syncthreads();
    if (tid == 0) {
        float S = 0.f, SQ = 0.f;
        #pragma unroll
        for (int i = 0; i < 8; i++) { S += red[i]; SQ += red2[i]; }
        float mean = S * (1.0f / Dq);
        float var  = SQ * (1.0f / Dq) - mean * mean;
        stats[0] = mean;
        stats[1] = rsqrtf(var + 1e-5f);
    }
    __syncthreads();
    float mean = stats[0], r = stats[1];
    const float* mrow = mod + (size_t)(t >> 6) * MODW;
    float* yr = Y + (size_t)t * Dq;
    yr[tid]       = (v0 - mean) * r * (1.0f + mrow[scaleOff + tid])       + mrow[shiftOff + tid];
    yr[tid + 256] = (v1 - mean) * r * (1.0f + mrow[scaleOff + tid + 256]) + mrow[shiftOff + tid + 256];
    yr[tid + 512] = (v2 - mean) * r * (1.0f + mrow[scaleOff + tid + 512]) + mrow[shiftOff + tid + 512];
}

// ---------------- tf32 mma.sync GEMM ------------------------------------------
// C[M,N] = epi(A[M,K] @ Bt[N,K]^T + bias)
// EPI 0: +bias   EPI 1: mish(+bias)   EPI 2: resid + gate*(+bias)
// CTA tile 128x128, BK=32, 8 warps (4 m x 2 n), warp tile 32x64.
// smem layout per 128x32 tile: row-major fp32, 16B groups swizzled q^=(row&7).
#define TILE_M 128
#define TILE_N 128
#define TILE_K 32
#define SMEM_GEMM 65536

__device__ __forceinline__ void stage_tile(const float* __restrict__ g, int ldg,
                                           uint32_t dstBase, int tid) {
    #pragma unroll
    for (int i = 0; i < 4; i++) {
        int idx = tid + i * 256;
        int row = idx >> 3, q = idx & 7;
        uint32_t dst = dstBase + row * 128 + ((q ^ (row & 7)) << 4);
        const float* src = g + (size_t)row * ldg + q * 4;
        asm volatile("cp.async.cg.shared.global [%0], [%1], 16;" :: "r"(dst), "l"(src));
    }
}

template <int EPI>
__global__ __launch_bounds__(256, 2)
void gemm_mma(const float* __restrict__ A, const float* __restrict__ Bt,
              const float* __restrict__ bias, float* __restrict__ C,
              int M, int N, int K,
              const float* __restrict__ mod, int modOff,
              const float* __restrict__ resid) {
    extern __shared__ char smem[];
    const uint32_t sb = smem_u32(smem);
    const int tid  = threadIdx.x;
    const int lane = tid & 31;
    const int warp = tid >> 5;
    const int grp  = lane >> 2;    // 0..7
    const int tig  = lane & 3;     // 0..3
    const int warpM = warp & 3;    // 0..3 -> 32-row slice
    const int warpN = warp >> 2;   // 0..1 -> 64-col slice
    const int mBase = blockIdx.y * TILE_M;
    const int nBase = blockIdx.x * TILE_N;

    const uint32_t aOff[2] = {0u, 16384u};
    const uint32_t bOff[2] = {32768u, 49152u};

    float d[2][8][4];
    #pragma unroll
    for (int mi = 0; mi < 2; mi++)
        #pragma unroll
        for (int nj = 0; nj < 8; nj++)
            #pragma unroll
            for (int r = 0; r < 4; r++) d[mi][nj][r] = 0.f;

    const float* Abase = A  + (size_t)mBase * K;
    const float* Bbase = Bt + (size_t)nBase * K;
    const int NC = K / TILE_K;

    // prefetch chunk 0
    stage_tile(Abase, K, sb + aOff[0], tid);
    stage_tile(Bbase, K, sb + bOff[0], tid);
    asm volatile("cp.async.commit_group;");

    for (int c = 0; c < NC; c++) {
        if (c + 1 < NC) {
            int nb = (c + 1) & 1;
            stage_tile(Abase + (c + 1) * TILE_K, K, sb + aOff[nb], tid);
            stage_tile(Bbase + (c + 1) * TILE_K, K, sb + bOff[nb], tid);
            asm volatile("cp.async.commit_group;");
            asm volatile("cp.async.wait_group 1;");
        } else {
            asm volatile("cp.async.wait_group 0;");
        }
        __syncthreads();

        const uint32_t* As = (const uint32_t*)(smem + aOff[c & 1]);
        const uint32_t* Bs = (const uint32_t*)(smem + bOff[c & 1]);
        #pragma unroll
        for (int kk = 0; kk < 4; kk++) {
            const int q0 = 2 * kk, q1 = 2 * kk + 1;
            uint32_t a[2][4];
            #pragma unroll
            for (int mi = 0; mi < 2; mi++) {
                int mA = warpM * 32 + mi * 16 + grp;
                int mB = mA + 8;
                a[mi][0] = As[mA * 32 + ((q0 ^ (mA & 7)) << 2) + tig];
                a[mi][1] = As[mB * 32 + ((q0 ^ (mB & 7)) << 2) + tig];
                a[mi][2] = As[mA * 32 + ((q1 ^ (mA & 7)) << 2) + tig];
                a[mi][3] = As[mB * 32 + ((q1 ^ (mB & 7)) << 2) + tig];
            }
            #pragma unroll
            for (int nj = 0; nj < 8; nj++) {
                int nn = warpN * 64 + nj * 8 + grp;
                uint32_t b0 = Bs[nn * 32 + ((q0 ^ (nn & 7)) << 2) + tig];
                uint32_t b1 = Bs[nn * 32 + ((q1 ^ (nn & 7)) << 2) + tig];
                #pragma unroll
                for (int mi = 0; mi < 2; mi++) {
                    asm volatile(
                        "mma.sync.aligned.m16n8k8.row.col.f32.tf32.tf32.f32 "
                        "{%0,%1,%2,%3}, {%4,%5,%6,%7}, {%8,%9}, {%0,%1,%2,%3};"
                        : "+f"(d[mi][nj][0]), "+f"(d[mi][nj][1]),
                          "+f"(d[mi][nj][2]), "+f"(d[mi][nj][3])
                        : "r"(a[mi][0]), "r"(a[mi][1]), "r"(a[mi][2]), "r"(a[mi][3]),
                          "r"(b0), "r"(b1));
                }
            }
        }
        __syncthreads();
    }

    // ---------------- epilogue ------------------------------------------------
    const int m0 = mBase + warpM * 32;
    const int n0 = nBase + warpN * 64;
    const float* modrow = (EPI == 2) ? (mod + (size_t)(m0 >> 6) * MODW + modOff) : nullptr;

    #pragma unroll
    for (int nj = 0; nj < 8; nj++) {
        int n = n0 + nj * 8 + tig * 2;
        float bv0 = __ldg(bias + n);
        float bv1 = __ldg(bias + n + 1);
        float g0 = 0.f, g1 = 0.f;
        if (EPI == 2) { g0 = modrow[n]; g1 = modrow[n + 1]; }
        #pragma unroll
        for (int mi = 0; mi < 2; mi++) {
            int m = m0 + mi * 16 + grp;
            #pragma unroll
            for (int hh = 0; hh < 2; hh++) {       // hh=0 -> row m, hh=1 -> row m+8
                int mm = m + hh * 8;
                float v0 = d[mi][nj][hh * 2 + 0] + bv0;
                float v1 = d[mi][nj][hh * 2 + 1] + bv1;
                if (EPI == 1) {
                    v0 = mishf(v0);
                    v1 = mishf(v1);
                } else if (EPI == 2) {
                    const float2 rr = *(const float2*)(resid + (size_t)mm * N + n);
                    v0 = rr.x + g0 * v0;
                    v1 = rr.y + g1 * v1;
                }
                *(float2*)(C + (size_t)mm * N + n) = make_float2(v0, v1);
            }
        }
    }
}

// ---------------- attention (fp32, unchanged) ---------------------------------
__global__ __launch_bounds__(256)
void attn_kernel(const float* __restrict__ QKV, float* __restrict__ O) {
    __shared__ float qs [64][64];
    __shared__ float ksT[64][64];
    __shared__ float psT[64][64];
    int h   = blockIdx.x;
    int b   = blockIdx.y;
    int tid = threadIdx.x;
    size_t base = (size_t)b * 64 * (3 * Dq) + (size_t)h * HDq;

    #pragma unroll
    for (int it = 0; it < 4; it++) {
        int idx = tid + it * 256;
        int row = idx >> 4;
        int cg  = idx & 15;
        float4 q4 = *reinterpret_cast<const float4*>(QKV + base + (size_t)row * (3 * Dq) + cg * 4);
        *reinterpret_cast<float4*>(&qs[row][cg * 4]) = q4;
        float4 k4 = *reinterpret_cast<const float4*>(QKV + base + (size_t)row * (3 * Dq) + Dq + cg * 4);
        ksT[cg * 4 + 0][row] = k4.x;
        ksT[cg * 4 + 1][row] = k4.y;
        ksT[cg * 4 + 2][row] = k4.z;
        ksT[cg * 4 + 3][row] = k4.w;
    }
    __syncthreads();

    int i  = tid >> 2;
    int jg = tid & 3;
    float sc[16];
    #pragma unroll
    for (int jj = 0; jj < 16; jj++) {
        int j = jg * 16 + jj;
        float acc = 0.f;
        #pragma unroll
        for (int d = 0; d < 64; d++) acc += qs[i][d] * ksT[d][j];
        sc[jj] = acc * 0.125f;
    }
    float mx = sc[0];
    #pragma unroll
    for (int jj = 1; jj < 16; jj++) mx = fmaxf(mx, sc[jj]);
    mx = fmaxf(mx, __shfl_xor_sync(0xffffffffu, mx, 1));
    mx = fmaxf(mx, __shfl_xor_sync(0xffffffffu, mx, 2));
    float sum = 0.f;
    #pragma unroll
    for (int jj = 0; jj < 16; jj++) { sc[jj] = __expf(sc[jj] - mx); sum += sc[jj]; }
    sum += __shfl_xor_sync(0xffffffffu, sum, 1);
    sum += __shfl_xor_sync(0xffffffffu, sum, 2);
    float rinv = 1.0f / sum;
    #pragma unroll
    for (int jj = 0; jj < 16; jj++) psT[jg * 16 + jj][i] = sc[jj] * rinv;
    __syncthreads();

    #pragma unroll
    for (int it = 0; it < 4; it++) {
        int idx = tid + it * 256;
        int row = idx >> 4;
        int cg  = idx & 15;
        *reinterpret_cast<float4*>(&qs[row][cg * 4]) =
            *reinterpret_cast<const float4*>(QKV + base + (size_t)row * (3 * Dq) + 2 * Dq + cg * 4);
    }
    __syncthreads();

    int d0 = (tid & 3) * 16;
    float o[16];
    #pragma unroll
    for (int dd = 0; dd < 16; dd++) o[dd] = 0.f;
    #pragma unroll
    for (int j = 0; j < 64; j++) {
        float p = psT[j][i];
        #pragma unroll
        for (int dd = 0; dd < 16; dd++) o[dd] += p * qs[j][d0 + dd];
    }
    float* orow = O + (size_t)(b * 64 + i) * Dq + h * HDq + d0;
    #pragma unroll
    for (int dd = 0; dd < 16; dd += 4)
        *reinterpret_cast<float4*>(orow + dd) = make_float4(o[dd], o[dd + 1], o[dd + 2], o[dd + 3]);
}

// ---------------- launch ------------------------------------------------------
extern "C" void kernel_launch(void* const* d_in, const int* in_sizes, int n_in,
                              void* d_out, int out_size) {
    const float* x     = (const float*)d_in[0];
    const float* c     = (const float*)d_in[1];
    const float* W_mod = (const float*)d_in[2];
    const float* b_mod = (const float*)d_in[3];
    const float* W_qkv = (const float*)d_in[4];
    const float* b_qkv = (const float*)d_in[5];
    const float* W_out = (const float*)d_in[6];
    const float* b_out = (const float*)d_in[7];
    const float* W_f1  = (const float*)d_in[8];
    const float* b_f1  = (const float*)d_in[9];
    const float* W_f2  = (const float*)d_in[10];
    const float* b_f2  = (const float*)d_in[11];
    float* out = (float*)d_out;

    float *mishc, *modp, *hbuf, *qkv, *attn, *x2, *ffn, *wt;
    cudaGetSymbolAddress((void**)&mishc, g_mishc);
    cudaGetSymbolAddress((void**)&modp,  g_mod);
    cudaGetSymbolAddress((void**)&hbuf,  g_h);
    cudaGetSymbolAddress((void**)&qkv,   g_qkv);
    cudaGetSymbolAddress((void**)&attn,  g_attn);
    cudaGetSymbolAddress((void**)&x2,    g_x2);
    cudaGetSymbolAddress((void**)&ffn,   g_ffn);
    cudaGetSymbolAddress((void**)&wt,    g_wt);

    cudaFuncSetAttribute(gemm_mma<0>, cudaFuncAttributeMaxDynamicSharedMemorySize, SMEM_GEMM);
    cudaFuncSetAttribute(gemm_mma<1>, cudaFuncAttributeMaxDynamicSharedMemorySize, SMEM_GEMM);
    cudaFuncSetAttribute(gemm_mma<2>, cudaFuncAttributeMaxDynamicSharedMemorySize, SMEM_GEMM);

    // weight transposes ([K,N] -> [N,K])
    transpose_k<<<dim3(2304 / 32, 768 / 32),  dim3(32, 8)>>>(W_qkv, wt + WT_QKV_OFF, 768, 2304);
    transpose_k<<<dim3(768 / 32,  768 / 32),  dim3(32, 8)>>>(W_out, wt + WT_OUT_OFF, 768, 768);
    transpose_k<<<dim3(3072 / 32, 768 / 32),  dim3(32, 8)>>>(W_f1,  wt + WT_F1_OFF,  768, 3072);
    transpose_k<<<dim3(768 / 32,  3072 / 32), dim3(32, 8)>>>(W_f2,  wt + WT_F2_OFF,  3072, 768);
    transpose_k<<<dim3(4608 / 32, 768 / 32),  dim3(32, 8)>>>(W_mod, wt + WT_MOD_OFF, 768, 4608);

    // 1) mish(c)
    mish_kernel<<<(Bq * Dq + 255) / 256, 256>>>(c, mishc, Bq * Dq);
    // 2) mod = mish(c) @ W_mod + b_mod
    gemm_mma<0><<<dim3(MODW / TILE_N, Bq / TILE_M), 256, SMEM_GEMM>>>(
        mishc, wt + WT_MOD_OFF, b_mod, modp, Bq, MODW, Dq, nullptr, 0, nullptr);
    // 3) h1 = LN(x)*(1+scale1)+shift1
    ln_mod_kernel<<<BSq, 256>>>(x, modp, hbuf, 0, Dq);
    // 4) qkv = h1 @ W_qkv + b_qkv
    gemm_mma<0><<<dim3(3 * Dq / TILE_N, BSq / TILE_M), 256, SMEM_GEMM>>>(
        hbuf, wt + WT_QKV_OFF, b_qkv, qkv, BSq, 3 * Dq, Dq, nullptr, 0, nullptr);
    // 5) attention
    attn_kernel<<<dim3(NHq, Bq), 256>>>(qkv, attn);
    // 6) x2 = x + gate1 * (attn @ W_out + b_out)
    gemm_mma<2><<<dim3(Dq / TILE_N, BSq / TILE_M), 256, SMEM_GEMM>>>(
        attn, wt + WT_OUT_OFF, b_out, x2, BSq, Dq, Dq, modp, 2 * Dq, x);
    // 7) h2 = LN(x2)*(1+scale2)+shift2
    ln_mod_kernel<<<BSq, 256>>>(x2, modp, hbuf, 3 * Dq, 4 * Dq);
    // 8) ffn = mish(h2 @ W_f1 + b_f1)
    gemm_mma<1><<<dim3(HIDq / TILE_N, BSq / TILE_M), 256, SMEM_GEMM>>>(
        hbuf, wt + WT_F1_OFF, b_f1, ffn, BSq, HIDq, Dq, nullptr, 0, nullptr);
    // 9) out = x2 + gate2 * (ffn @ W_f2 + b_f2)
    gemm_mma<2><<<dim3(Dq / TILE_N, BSq / TILE_M), 256, SMEM_GEMM>>>(
        ffn, wt + WT_F2_OFF, b_f2, out, BSq, Dq, HIDq, modp, 5 * Dq, x2);
}